// round 1
// baseline (speedup 1.0000x reference)
#include <cuda_runtime.h>
#include <cuda_bf16.h>

#define NB_ACTIONS 64
#define NB_ELEMS 2080           // 64*65/2
#define EPS 1e-7f

// One warp per batch row.
// quad = d^T (L L^T) d = || L^T d ||^2 ; y_j = sum_{i>=j} d_i * L[i,j]
// Packed tril layout: element (i,j), j<=i at offset i*(i+1)/2 + j (contiguous per row).
__global__ __launch_bounds__(256) void naf_kernel(
    const float* __restrict__ L_flat,
    const float* __restrict__ mu,
    const float* __restrict__ a,
    float* __restrict__ out,
    int batch)
{
    const int warp = (blockIdx.x * blockDim.x + threadIdx.x) >> 5;
    const int lane = threadIdx.x & 31;
    if (warp >= batch) return;

    const float* __restrict__ Lr = L_flat + (size_t)warp * NB_ELEMS;
    const float* __restrict__ ar = a  + (size_t)warp * NB_ACTIONS;
    const float* __restrict__ mr = mu + (size_t)warp * NB_ACTIONS;

    // d = a - mu ; lane holds d[lane] and d[lane+32]
    const float d0 = ar[lane]      - mr[lane];
    const float d1 = ar[lane + 32] - mr[lane + 32];

    float y0 = 0.0f;   // column j = lane
    float y1 = 0.0f;   // column j = lane + 32

    int off = 0;       // i*(i+1)/2, tracked incrementally
    #pragma unroll
    for (int i = 0; i < NB_ACTIONS; ++i) {
        const float di = (i < 32) ? __shfl_sync(0xffffffffu, d0, i)
                                  : __shfl_sync(0xffffffffu, d1, i - 32);

        // first 32 columns of row i
        float v0 = (lane <= i) ? Lr[off + lane] : 0.0f;
        if (i < 32 && lane == i) v0 = __expf(v0) + EPS;       // diagonal
        y0 = fmaf(di, v0, y0);

        if (i >= 32) {
            // columns 32..i of row i
            float v1 = (lane + 32 <= i) ? Lr[off + 32 + lane] : 0.0f;
            if (lane + 32 == i) v1 = __expf(v1) + EPS;        // diagonal
            y1 = fmaf(di, v1, y1);
        }
        off += i + 1;
    }

    // quad = sum_j y_j^2 ; warp butterfly reduction
    float q = fmaf(y0, y0, y1 * y1);
    #pragma unroll
    for (int s = 16; s > 0; s >>= 1)
        q += __shfl_xor_sync(0xffffffffu, q, s);

    if (lane == 0)
        out[warp] = -0.5f * q;
}

extern "C" void kernel_launch(void* const* d_in, const int* in_sizes, int n_in,
                              void* d_out, int out_size) {
    const float* L_flat = (const float*)d_in[0];
    const float* mu     = (const float*)d_in[1];
    const float* a      = (const float*)d_in[2];
    float* out          = (float*)d_out;

    const int batch = in_sizes[0] / NB_ELEMS;   // 32768

    const int threads = 256;                    // 8 warps -> 8 batches per block
    const int warps_per_block = threads / 32;
    const int blocks = (batch + warps_per_block - 1) / warps_per_block;
    naf_kernel<<<blocks, threads>>>(L_flat, mu, a, out, batch);
}

// round 2
// speedup vs baseline: 1.7526x; 1.7526x over previous
#include <cuda_runtime.h>
#include <cuda_bf16.h>
#include <cuda_pipeline.h>

#define NB_ACTIONS 64
#define NB_ELEMS 2080           // 64*65/2
#define EPS 1e-7f
#define WARPS_PER_BLOCK 4

// One warp per batch row.
// quad = d^T (L L^T) d = || L^T d ||^2 ; y_j = sum_{i>=j} d_i * L[i,j]
// Phase 1: stream the 2080-float packed-tril row into smem via cp.async
//          (17 independent 16B copies per lane -> high MLP, no reg pressure).
// Phase 2: triangular compute from smem with fully-unrolled loop
//          (LDS at base+immediate, no address math).
__global__ __launch_bounds__(WARPS_PER_BLOCK * 32) void naf_kernel(
    const float* __restrict__ L_flat,
    const float* __restrict__ mu,
    const float* __restrict__ a,
    float* __restrict__ out,
    int batch)
{
    __shared__ __align__(16) float sL[WARPS_PER_BLOCK][NB_ELEMS];

    const int wslot = threadIdx.x >> 5;
    const int lane  = threadIdx.x & 31;
    const int warp  = blockIdx.x * WARPS_PER_BLOCK + wslot;
    if (warp >= batch) return;

    const float* __restrict__ Lr = L_flat + (size_t)warp * NB_ELEMS;
    const float* __restrict__ ar = a  + (size_t)warp * NB_ACTIONS;
    const float* __restrict__ mr = mu + (size_t)warp * NB_ACTIONS;

    // ---- Phase 1: async copy 2080 floats = 520 float4 into smem ----
    {
        const float4* src = (const float4*)Lr;
        float4*       dst = (float4*)&sL[wslot][0];
        #pragma unroll
        for (int it = 0; it < 16; ++it)
            __pipeline_memcpy_async(&dst[it * 32 + lane], &src[it * 32 + lane], 16);
        if (lane < 8)
            __pipeline_memcpy_async(&dst[512 + lane], &src[512 + lane], 16);
        __pipeline_commit();
    }

    // d = a - mu ; lane holds d[lane] and d[lane+32]  (overlaps with cp.async)
    const float d0 = ar[lane]      - mr[lane];
    const float d1 = ar[lane + 32] - mr[lane + 32];

    __pipeline_wait_prior(0);
    __syncwarp();

    // ---- Phase 2: y_j = sum_{i>=j} d_i * L[i,j] from smem ----
    const float* __restrict__ s = &sL[wslot][0];
    float y0 = 0.0f;   // column j = lane
    float y1 = 0.0f;   // column j = lane + 32

    int off = 0;       // i*(i+1)/2 — compile-time constant after full unroll
    #pragma unroll
    for (int i = 0; i < NB_ACTIONS; ++i) {
        const float di = (i < 32) ? __shfl_sync(0xffffffffu, d0, i)
                                  : __shfl_sync(0xffffffffu, d1, i - 32);

        float v0 = (lane <= i) ? s[off + lane] : 0.0f;
        if (i < 32 && lane == i) v0 = __expf(v0) + EPS;       // diagonal
        y0 = fmaf(di, v0, y0);

        if (i >= 32) {
            float v1 = (lane + 32 <= i) ? s[off + 32 + lane] : 0.0f;
            if (lane + 32 == i) v1 = __expf(v1) + EPS;        // diagonal
            y1 = fmaf(di, v1, y1);
        }
        off += i + 1;
    }

    // quad = sum_j y_j^2 ; warp butterfly reduction
    float q = fmaf(y0, y0, y1 * y1);
    #pragma unroll
    for (int sft = 16; sft > 0; sft >>= 1)
        q += __shfl_xor_sync(0xffffffffu, q, sft);

    if (lane == 0)
        out[warp] = -0.5f * q;
}

extern "C" void kernel_launch(void* const* d_in, const int* in_sizes, int n_in,
                              void* d_out, int out_size) {
    const float* L_flat = (const float*)d_in[0];
    const float* mu     = (const float*)d_in[1];
    const float* a      = (const float*)d_in[2];
    float* out          = (float*)d_out;

    const int batch = in_sizes[0] / NB_ELEMS;   // 32768

    const int blocks = (batch + WARPS_PER_BLOCK - 1) / WARPS_PER_BLOCK;
    naf_kernel<<<blocks, WARPS_PER_BLOCK * 32>>>(L_flat, mu, a, out, batch);
}